// round 16
// baseline (speedup 1.0000x reference)
#include <cuda_runtime.h>
#include <cuda_fp16.h>
#include <mma.h>
#include <math.h>
#include <stdint.h>

using namespace nvcuda;

#define N_NODES 50000
#define N_EDGES 400000
#define MT_COUNT 392                 // padded row tiles: 392*128 = 50176
#define PAD_ROWS (MT_COUNT * 128)
#define SCAN_BLK 256
#define SCAN_NB ((N_NODES + SCAN_BLK - 1) / SCAN_BLK)

typedef unsigned int u32;
typedef unsigned long long u64;

// ---------------- scratch (static device globals; no allocs) ----------------
__device__ int   g_is64;
__device__ int   g_cnt[N_NODES];
__device__ int   g_off[N_NODES + 1];
__device__ int   g_cur[N_NODES];
__device__ int   g_srcs[N_EDGES];
__device__ int   g_bsum[SCAN_BLK];
__device__ float g_dinv[N_NODES];
__device__ float g_T[2 * N_NODES];
// fp16 activation ping-pong buffers, row-major [PAD_ROWS, <=512]
__device__ __half g_h0[(size_t)PAD_ROWS * 512];
__device__ __half g_h1[(size_t)PAD_ROWS * 512];
// x converted to fp16 [N_NODES,128]
__device__ __half g_xh[(size_t)N_NODES * 128];
// weights fp16
__device__ __half g_b1[128 * 256];
__device__ __half g_b2[256 * 512];
__device__ __half g_b3[512 * 256];
__device__ __half g_b4[256 * 64];

// ---------------- helpers ----------------
__device__ __forceinline__ u32 smem_u32(const void* p) {
    return (u32)__cvta_generic_to_shared(p);
}
__device__ __forceinline__ void cp_async16(u32 dst, const void* src) {
    asm volatile("cp.async.cg.shared.global [%0], [%1], 16;" :: "r"(dst), "l"(src));
}
__device__ __forceinline__ void cp_commit() {
    asm volatile("cp.async.commit_group;" ::: "memory");
}
__device__ __forceinline__ void cp_wait_dyn(int n) {
    if (n <= 0)      asm volatile("cp.async.wait_group 0;" ::: "memory");
    else if (n == 1) asm volatile("cp.async.wait_group 1;" ::: "memory");
    else             asm volatile("cp.async.wait_group 2;" ::: "memory");
}
template <int F2>
__device__ __forceinline__ void load_h2v(const __half2* p, __half2* v) {
    if (F2 == 1)      *(u32*)v  = *(const u32*)p;
    else if (F2 == 2) *(uint2*)v = *(const uint2*)p;
    else              *(uint4*)v = *(const uint4*)p;
}
template <int F2>
__device__ __forceinline__ void store_h2v(__half2* p, const __half2* v) {
    if (F2 == 1)      *(u32*)p  = *(const u32*)v;
    else if (F2 == 2) *(uint2*)p = *(const uint2*)v;
    else              *(uint4*)p = *(const uint4*)v;
}

// ---------------- edge dtype detection (warp-parallel) ----------------
__global__ void detect_kernel(const void* eiv) {
    const long long* p = (const long long*)eiv;
    int t = threadIdx.x;
    int bad = 0;
    #pragma unroll
    for (int e = t; e < 256; e += 32) {
        long long v = p[e];
        if (v < 0 || v >= N_NODES) bad = 1;
    }
    unsigned m = __ballot_sync(0xFFFFFFFFu, bad);
    if (t == 0) g_is64 = (m == 0u);
}
__device__ __forceinline__ int load_src(const void* eiv, int E, int e) {
    return g_is64 ? (int)((const long long*)eiv)[e] : ((const int*)eiv)[e];
}
__device__ __forceinline__ int load_dst(const void* eiv, int E, int e) {
    return g_is64 ? (int)((const long long*)eiv)[E + e] : ((const int*)eiv)[E + e];
}

// ---------------- preprocessing ----------------
__global__ void zero_cnt_kernel(int* cnt, int n) {
    int i = blockIdx.x * blockDim.x + threadIdx.x;
    if (i < n) cnt[i] = 0;
}

// ---------------- fused count + fp16 conversions ----------------
#define W1_SZ (128 * 256)
#define W2_SZ (256 * 512)
#define W3_SZ (512 * 256)
#define W4_SZ (256 * 64)
#define X_SZ  (N_NODES * 128)
#define CONV_TOTAL4 ((W1_SZ + W2_SZ + W3_SZ + W4_SZ + X_SZ) / 4)
#define CD_TOTAL (N_EDGES + CONV_TOTAL4)
__device__ __forceinline__ void conv4(const float* __restrict__ S, __half* __restrict__ D, int e4) {
    float4 v = *(const float4*)(S + 4 * e4);
    __half2 p0; p0.x = __float2half(v.x); p0.y = __float2half(v.y);
    __half2 p1; p1.x = __float2half(v.z); p1.y = __float2half(v.w);
    *(__half2*)(D + 4 * e4) = p0;
    *(__half2*)(D + 4 * e4 + 2) = p1;
}
__global__ void count_decomp_kernel(const void* __restrict__ eiv, int* __restrict__ cnt,
                                    const float* __restrict__ W1, const float* __restrict__ W2,
                                    const float* __restrict__ W3, const float* __restrict__ W4,
                                    const float* __restrict__ X,
                                    __half* __restrict__ B1, __half* __restrict__ B2,
                                    __half* __restrict__ B3, __half* __restrict__ B4,
                                    __half* __restrict__ XH) {
    int e = blockIdx.x * blockDim.x + threadIdx.x;
    if (e < N_EDGES) { atomicAdd(&cnt[load_dst(eiv, N_EDGES, e)], 1); return; }
    e -= N_EDGES;
    if (e < W1_SZ / 4) { conv4(W1, B1, e); return; }
    e -= W1_SZ / 4;
    if (e < W2_SZ / 4) { conv4(W2, B2, e); return; }
    e -= W2_SZ / 4;
    if (e < W3_SZ / 4) { conv4(W3, B3, e); return; }
    e -= W3_SZ / 4;
    if (e < W4_SZ / 4) { conv4(W4, B4, e); return; }
    e -= W4_SZ / 4;
    if (e < X_SZ / 4) conv4(X, XH, e);
}

__global__ void scan1_kernel(const int* __restrict__ cnt, int* __restrict__ off,
                             int* __restrict__ bsum, int n) {
    __shared__ int sh[SCAN_BLK];
    int t = threadIdx.x;
    int i = blockIdx.x * SCAN_BLK + t;
    int v = (i < n) ? cnt[i] : 0;
    sh[t] = v;
    __syncthreads();
    for (int d = 1; d < SCAN_BLK; d <<= 1) {
        int x = 0;
        if (t >= d) x = sh[t - d];
        __syncthreads();
        if (t >= d) sh[t] += x;
        __syncthreads();
    }
    if (i < n) off[i] = sh[t] - v;
    if (t == SCAN_BLK - 1) bsum[blockIdx.x] = sh[t];
}
__global__ void scan2_kernel(int* __restrict__ bsum, int* __restrict__ off, int nb, int n) {
    __shared__ int sh[SCAN_BLK];
    int t = threadIdx.x;
    int v = (t < nb) ? bsum[t] : 0;
    sh[t] = v;
    __syncthreads();
    for (int d = 1; d < SCAN_BLK; d <<= 1) {
        int x = 0;
        if (t >= d) x = sh[t - d];
        __syncthreads();
        if (t >= d) sh[t] += x;
        __syncthreads();
    }
    if (t < nb) bsum[t] = sh[t] - v;
    if (t == nb - 1) off[n] = sh[t];
}
__global__ void scan3_kernel(const int* __restrict__ cnt, int* __restrict__ off,
                             int* __restrict__ cur, float* __restrict__ dinv,
                             const int* __restrict__ bsum, int n) {
    int i = blockIdx.x * blockDim.x + threadIdx.x;
    if (i < n) {
        int o = off[i] + bsum[i >> 8];
        off[i] = o;
        cur[i] = o;
        dinv[i] = rsqrtf((float)(cnt[i] + 1));
    }
}
__global__ void fill_kernel(const void* __restrict__ eiv, int* cur,
                            int* __restrict__ srcs, int E) {
    int e = blockIdx.x * blockDim.x + threadIdx.x;
    if (e < E) {
        int d = load_dst(eiv, E, e);
        int pos = atomicAdd(&cur[d], 1);
        srcs[pos] = load_src(eiv, E, e);
    }
}
__global__ void sortseg_kernel(const int* __restrict__ off, int* __restrict__ srcs, int n) {
    int i = blockIdx.x * blockDim.x + threadIdx.x;
    if (i >= n) return;
    int s0 = off[i], s1 = off[i + 1];
    for (int a = s0 + 1; a < s1; ++a) {
        int key = srcs[a];
        int b = a - 1;
        while (b >= s0 && srcs[b] > key) { srcs[b + 1] = srcs[b]; --b; }
        srcs[b + 1] = key;
    }
}

// ---------------- aggregation (fp16 in, fp16 out, fp32 accumulate) ----------------
template <int D>
__global__ __launch_bounds__(256) void agg_h_kernel(
    const __half* __restrict__ H,
    const int* __restrict__ off, const int* __restrict__ srcs,
    const float* __restrict__ dinv,
    const float* __restrict__ bias, int doRelu,
    __half* __restrict__ Oh) {
    constexpr int F2 = D / 64;          // half2 per lane
    int lane = threadIdx.x & 31;
    int i = blockIdx.x * 8 + (threadIdx.x >> 5);
    if (i >= N_NODES) return;

    float di = dinv[i];
    float2 acc[F2], acc2[F2];
    {
        __half2 h[F2];
        load_h2v<F2>((const __half2*)(H + (size_t)i * D) + lane * F2, h);
        #pragma unroll
        for (int j = 0; j < F2; ++j) {
            float2 f = __half22float2(h[j]);
            acc[j].x = di * f.x; acc[j].y = di * f.y;
            acc2[j].x = 0.0f; acc2[j].y = 0.0f;
        }
    }
    int s0 = off[i], s1 = off[i + 1];
    for (int base = s0; base < s1; base += 32) {
        int nb = s1 - base; if (nb > 32) nb = 32;
        int sid = 0; float wv = 0.0f;
        if (lane < nb) { sid = srcs[base + lane]; wv = dinv[sid]; }
        int e = 0;
        for (; e + 1 < nb; e += 2) {
            int sa = __shfl_sync(0xFFFFFFFFu, sid, e);
            float wa = __shfl_sync(0xFFFFFFFFu, wv, e);
            int sb = __shfl_sync(0xFFFFFFFFu, sid, e + 1);
            float wb = __shfl_sync(0xFFFFFFFFu, wv, e + 1);
            __half2 ha[F2], hb[F2];
            load_h2v<F2>((const __half2*)(H + (size_t)sa * D) + lane * F2, ha);
            load_h2v<F2>((const __half2*)(H + (size_t)sb * D) + lane * F2, hb);
            #pragma unroll
            for (int j = 0; j < F2; ++j) {
                float2 fa = __half22float2(ha[j]);
                float2 fb = __half22float2(hb[j]);
                acc[j].x  = fmaf(wa, fa.x, acc[j].x);
                acc[j].y  = fmaf(wa, fa.y, acc[j].y);
                acc2[j].x = fmaf(wb, fb.x, acc2[j].x);
                acc2[j].y = fmaf(wb, fb.y, acc2[j].y);
            }
        }
        if (e < nb) {
            int sa = __shfl_sync(0xFFFFFFFFu, sid, e);
            float wa = __shfl_sync(0xFFFFFFFFu, wv, e);
            __half2 ha[F2];
            load_h2v<F2>((const __half2*)(H + (size_t)sa * D) + lane * F2, ha);
            #pragma unroll
            for (int j = 0; j < F2; ++j) {
                float2 fa = __half22float2(ha[j]);
                acc[j].x = fmaf(wa, fa.x, acc[j].x);
                acc[j].y = fmaf(wa, fa.y, acc[j].y);
            }
        }
    }
    __half2 oh[F2];
    #pragma unroll
    for (int j = 0; j < F2; ++j) {
        float v0 = di * (acc[j].x + acc2[j].x);
        float v1 = di * (acc[j].y + acc2[j].y);
        if (bias) {
            v0 += bias[(lane * F2 + j) * 2];
            v1 += bias[(lane * F2 + j) * 2 + 1];
        }
        if (doRelu) { v0 = fmaxf(v0, 0.0f); v1 = fmaxf(v1, 0.0f); }
        float2 vo; vo.x = v0; vo.y = v1;
        oh[j] = __float22half2_rn(vo);
    }
    store_h2v<F2>((__half2*)(Oh + (size_t)i * D) + lane * F2, oh);
}

// ---------------- fused L4 agg + [64,2] GEMM ----------------
__global__ __launch_bounds__(256) void agg64_gemm2_kernel(
    const __half* __restrict__ H,
    const int* __restrict__ off, const int* __restrict__ srcs,
    const float* __restrict__ dinv,
    const float* __restrict__ b4, const float* __restrict__ W5,
    float* __restrict__ T, int nTotal) {
    int lane = threadIdx.x & 31;
    int i = blockIdx.x * 8 + (threadIdx.x >> 5);
    if (i >= nTotal) return;
    float di = dinv[i];
    float2 f = __half22float2(*((const __half2*)(H + (size_t)i * 64) + lane));
    float a0 = di * f.x, a1 = di * f.y, c0 = 0.f, c1 = 0.f;
    int s0 = off[i], s1 = off[i + 1];
    for (int base = s0; base < s1; base += 32) {
        int nb = s1 - base; if (nb > 32) nb = 32;
        int sid = 0; float wv = 0.0f;
        if (lane < nb) { sid = srcs[base + lane]; wv = dinv[sid]; }
        int e = 0;
        for (; e + 1 < nb; e += 2) {
            int sa = __shfl_sync(0xFFFFFFFFu, sid, e);
            float wa = __shfl_sync(0xFFFFFFFFu, wv, e);
            int sb = __shfl_sync(0xFFFFFFFFu, sid, e + 1);
            float wb = __shfl_sync(0xFFFFFFFFu, wv, e + 1);
            float2 fa = __half22float2(*((const __half2*)(H + (size_t)sa * 64) + lane));
            float2 fb = __half22float2(*((const __half2*)(H + (size_t)sb * 64) + lane));
            a0 = fmaf(wa, fa.x, a0); a1 = fmaf(wa, fa.y, a1);
            c0 = fmaf(wb, fb.x, c0); c1 = fmaf(wb, fb.y, c1);
        }
        if (e < nb) {
            int sa = __shfl_sync(0xFFFFFFFFu, sid, e);
            float wa = __shfl_sync(0xFFFFFFFFu, wv, e);
            float2 fa = __half22float2(*((const __half2*)(H + (size_t)sa * 64) + lane));
            a0 = fmaf(wa, fa.x, a0); a1 = fmaf(wa, fa.y, a1);
        }
    }
    float v0 = di * (a0 + c0) + b4[lane * 2];
    float v1 = di * (a1 + c1) + b4[lane * 2 + 1];
    v0 = fmaxf(v0, 0.0f); v1 = fmaxf(v1, 0.0f);
    float4 w = *(const float4*)(W5 + 4 * lane);
    float p0 = v0 * w.x + v1 * w.z;
    float p1 = v0 * w.y + v1 * w.w;
    #pragma unroll
    for (int o = 16; o > 0; o >>= 1) {
        p0 += __shfl_down_sync(0xFFFFFFFFu, p0, o);
        p1 += __shfl_down_sync(0xFFFFFFFFu, p1, o);
    }
    if (lane == 0) { T[2 * i] = p0; T[2 * i + 1] = p1; }
}

// ---------------- BIG-TILE WMMA GEMM: CTA 128x256, warp 64x64, BK=32 ----------------
// 8 warps (2 m x 4 n). Per kf-step: 8 LDSM feed 16 HMMA (2x density of 32x64 warps).
// ~210 regs/thread -> 1 CTA/SM (cutlass operating point). Epilogue: two 128x128
// fp32 smem passes.
__global__ __launch_bounds__(256, 1) void gemm_big_kernel(
    const __half* __restrict__ Ah, const __half* __restrict__ Bh,
    const float* __restrict__ bias, int doRelu,
    __half* __restrict__ Oh, int K, int N) {
    constexpr int BN = 256;
    constexpr int A_LD = 40;             // 32 + 8 pad
    constexpr int B_LD = BN + 8;         // 264
    constexpr int A_BYTES = 128 * A_LD * 2;   // 10240
    constexpr int STAGE = A_BYTES + 32 * B_LD * 2;  // 27136

    extern __shared__ char sm[];
    int tid = threadIdx.x;
    int wid = tid >> 5;
    int mt = blockIdx.x, nt = blockIdx.y;
    int row0 = mt * 128, bn0 = nt * BN;
    int total = K >> 5;

    auto As = [&](int s) { return (__half*)(sm + s * STAGE); };
    auto Bs = [&](int s) { return (__half*)(sm + s * STAGE + A_BYTES); };

    auto issue = [&](int u) {
        int s = u % 3;
        int k0 = u << 5;
        // A: 128x32 halves = 512 16B-chunks, 2/thread
        #pragma unroll
        for (int c = 0; c < 2; ++c) {
            int chunk = tid + c * 256;
            int row = chunk >> 2, col8 = (chunk & 3) * 8;
            cp_async16(smem_u32(As(s) + row * A_LD + col8),
                       Ah + (size_t)(row0 + row) * K + k0 + col8);
        }
        // B: 32x256 halves = 1024 16B-chunks, 4/thread
        #pragma unroll
        for (int c = 0; c < 4; ++c) {
            int chunk = tid + c * 256;
            int r = chunk >> 5, c8 = (chunk & 31) * 8;
            cp_async16(smem_u32(Bs(s) + r * B_LD + c8),
                       Bh + (size_t)(k0 + r) * N + bn0 + c8);
        }
        cp_commit();
    };

    int wm = (wid & 1) * 64;      // 2 warps in m
    int wn = (wid >> 1) * 64;     // 4 warps in n

    wmma::fragment<wmma::accumulator, 16, 16, 16, float> acc[4][4];
    #pragma unroll
    for (int mi = 0; mi < 4; ++mi)
        #pragma unroll
        for (int ni = 0; ni < 4; ++ni) wmma::fill_fragment(acc[mi][ni], 0.0f);

    int issued = 0;
    for (int p = 0; p < 2 && issued < total; ++p) issue(issued++);
    for (int u = 0; u < total; ++u) {
        cp_wait_dyn(issued - u - 1);
        __syncthreads();   // stage u visible; ring slot (u+2)%3 free to refill
        if (issued < total) issue(issued++);
        int s = u % 3;
        const __half* a = As(s);
        const __half* b = Bs(s);
        #pragma unroll
        for (int kf = 0; kf < 2; ++kf) {
            wmma::fragment<wmma::matrix_a, 16, 16, 16, __half, wmma::row_major> af[4];
            wmma::fragment<wmma::matrix_b, 16, 16, 16, __half, wmma::row_major> bf[4];
            #pragma unroll
            for (int mi = 0; mi < 4; ++mi)
                wmma::load_matrix_sync(af[mi], a + (wm + mi * 16) * A_LD + kf * 16, A_LD);
            #pragma unroll
            for (int ni = 0; ni < 4; ++ni)
                wmma::load_matrix_sync(bf[ni], b + (kf * 16) * B_LD + wn + ni * 16, B_LD);
            #pragma unroll
            for (int mi = 0; mi < 4; ++mi)
                #pragma unroll
                for (int ni = 0; ni < 4; ++ni)
                    wmma::mma_sync(acc[mi][ni], af[mi], bf[ni], acc[mi][ni]);
        }
    }
    __syncthreads();   // protect epilogue smem reuse

    // epilogue: two 128x128 fp32 passes through smem (64 KB <= 81.4 KB alloc)
    float* Cs = (float*)sm;
    #pragma unroll
    for (int half = 0; half < 2; ++half) {
        if ((wid >> 2) == half) {
            int wnl = wn - half * 128;
            #pragma unroll
            for (int mi = 0; mi < 4; ++mi)
                #pragma unroll
                for (int ni = 0; ni < 4; ++ni)
                    wmma::store_matrix_sync(Cs + (wm + mi * 16) * 128 + wnl + ni * 16,
                                            acc[mi][ni], 128, wmma::mem_row_major);
        }
        __syncthreads();
        int nbase = bn0 + half * 128;
        for (int idx2 = tid; idx2 < 128 * 64; idx2 += 256) {
            int r = idx2 >> 6, c2 = idx2 & 63;
            float v0 = Cs[r * 128 + 2 * c2];
            float v1 = Cs[r * 128 + 2 * c2 + 1];
            if (bias) { v0 += bias[nbase + 2 * c2]; v1 += bias[nbase + 2 * c2 + 1]; }
            if (doRelu) { v0 = fmaxf(v0, 0.0f); v1 = fmaxf(v1, 0.0f); }
            __half2 p; p.x = __float2half(v0); p.y = __float2half(v1);
            *(__half2*)(Oh + (size_t)(row0 + r) * N + nbase + 2 * c2) = p;
        }
        __syncthreads();
    }
}

// ---------------- WMMA fp16 GEMM BN=64 (L4 only), BK=32, 3-stage ----------------
__global__ __launch_bounds__(256) void gemm_n64_kernel(
    const __half* __restrict__ Ah, const __half* __restrict__ Bh,
    __half* __restrict__ Oh, int K, int N) {
    constexpr int BN = 64;
    constexpr int A_LD = 40;
    constexpr int B_LD = BN + 8;
    constexpr int A_BYTES = 128 * A_LD * 2;
    constexpr int STAGE = A_BYTES + 32 * B_LD * 2;
    constexpr int WN = 32;
    constexpr int NF = 2;

    extern __shared__ char sm[];
    int tid = threadIdx.x;
    int wid = tid >> 5;
    int mt = blockIdx.x;
    int row0 = mt * 128;
    int total = K >> 5;

    auto As = [&](int s) { return (__half*)(sm + s * STAGE); };
    auto Bs = [&](int s) { return (__half*)(sm + s * STAGE + A_BYTES); };

    auto issue = [&](int u) {
        int s = u % 3;
        int k0 = u << 5;
        #pragma unroll
        for (int c = 0; c < 2; ++c) {
            int chunk = tid + c * 256;
            int row = chunk >> 2, col8 = (chunk & 3) * 8;
            cp_async16(smem_u32(As(s) + row * A_LD + col8),
                       Ah + (size_t)(row0 + row) * K + k0 + col8);
        }
        {
            int r = tid >> 3, c8 = (tid & 7) * 8;
            cp_async16(smem_u32(Bs(s) + r * B_LD + c8),
                       Bh + (size_t)(k0 + r) * N + c8);
        }
        cp_commit();
    };

    int wm = (wid & 3) * 32;
    int wn = (wid >> 2) * WN;

    wmma::fragment<wmma::accumulator, 16, 16, 16, float> acc[2][NF];
    #pragma unroll
    for (int mi = 0; mi < 2; ++mi)
        #pragma unroll
        for (int ni = 0; ni < NF; ++ni) wmma::fill_fragment(acc[mi][ni], 0.0f);

    int issued = 0;
    for (int p = 0; p < 2 && issued < total; ++p) issue(issued++);
    for (int u = 0; u < total; ++u) {
        cp_wait_dyn(issued - u - 1);
        __syncthreads();
        if (issued < total) issue(issued++);
        int s = u % 3;
        const __half* a = As(s);
        const __half* b = Bs(s);
        #pragma unroll
        for (int kf = 0; kf < 2; ++kf) {
            wmma::fragment<wmma::matrix_a, 16, 16, 16, __half, wmma::row_major> af[2];
            wmma::fragment<wmma::matrix_b, 16, 16, 16, __half, wmma::row_major> bf[NF];
            #pragma unroll
            for (int mi = 0; mi < 2; ++mi)
                wmma::load_matrix_sync(af[mi], a + (wm + mi * 16) * A_LD + kf * 16, A_LD);
            #pragma unroll
            for (int ni = 0; ni < NF; ++ni)
                wmma::load_matrix_sync(bf[ni], b + (kf * 16) * B_LD + wn + ni * 16, B_LD);
            #pragma unroll
            for (int mi = 0; mi < 2; ++mi)
                #pragma unroll
                for (int ni = 0; ni < NF; ++ni)
                    wmma::mma_sync(acc[mi][ni], af[mi], bf[ni], acc[mi][ni]);
        }
    }
    __syncthreads();

    float* Cs = (float*)sm;
    #pragma unroll
    for (int mi = 0; mi < 2; ++mi)
        #pragma unroll
        for (int ni = 0; ni < NF; ++ni)
            wmma::store_matrix_sync(Cs + (wm + mi * 16) * BN + wn + ni * 16,
                                    acc[mi][ni], BN, wmma::mem_row_major);
    __syncthreads();

    for (int idx2 = tid; idx2 < 128 * BN / 2; idx2 += 256) {
        int r = idx2 / (BN / 2), c2 = idx2 % (BN / 2);
        float v0 = Cs[r * BN + 2 * c2];
        float v1 = Cs[r * BN + 2 * c2 + 1];
        __half2 p; p.x = __float2half(v0); p.y = __float2half(v1);
        *(__half2*)(Oh + (size_t)(row0 + r) * N + 2 * c2) = p;
    }
}

// ---------------- final aggregation (dim 2) + bias + log_softmax ----------------
__global__ void agg2_lsm_kernel(const float* __restrict__ T, const float* __restrict__ b,
                                float* __restrict__ out,
                                const int* __restrict__ off, const int* __restrict__ srcs,
                                const float* __restrict__ dinv, int n) {
    int i = blockIdx.x * blockDim.x + threadIdx.x;
    if (i >= n) return;
    float di = dinv[i];
    float a0 = di * T[2 * i];
    float a1 = di * T[2 * i + 1];
    int s0 = off[i], s1 = off[i + 1];
    for (int e = s0; e < s1; ++e) {
        int s = srcs[e];
        float w = dinv[s];
        a0 = fmaf(w, T[2 * s], a0);
        a1 = fmaf(w, T[2 * s + 1], a1);
    }
    float z0 = fmaf(di, a0, b[0]);
    float z1 = fmaf(di, a1, b[1]);
    float m = fmaxf(z0, z1);
    float lse = m + logf(expf(z0 - m) + expf(z1 - m));
    out[2 * i] = z0 - lse;
    out[2 * i + 1] = z1 - lse;
}

// ---------------- host launch ----------------
extern "C" void kernel_launch(void* const* d_in, const int* in_sizes, int n_in,
                              void* d_out, int out_size) {
    const float* x  = (const float*)d_in[0];
    const void*  ei = d_in[1];
    const float* W1 = (const float*)d_in[2];  const float* b1 = (const float*)d_in[3];
    const float* W2 = (const float*)d_in[4];  const float* b2 = (const float*)d_in[5];
    const float* W3 = (const float*)d_in[6];  const float* b3 = (const float*)d_in[7];
    const float* W4 = (const float*)d_in[8];  const float* b4 = (const float*)d_in[9];
    const float* W5 = (const float*)d_in[10]; const float* b5 = (const float*)d_in[11];
    float* out = (float*)d_out;

    const int N = N_NODES;
    const int E = N_EDGES;

    int *cnt, *off, *cur, *srcs, *bsum;
    float *dinv, *T;
    __half *h0, *h1, *xh, *bb1, *bb2, *bb3, *bb4;
    cudaGetSymbolAddress((void**)&cnt,  g_cnt);
    cudaGetSymbolAddress((void**)&off,  g_off);
    cudaGetSymbolAddress((void**)&cur,  g_cur);
    cudaGetSymbolAddress((void**)&srcs, g_srcs);
    cudaGetSymbolAddress((void**)&bsum, g_bsum);
    cudaGetSymbolAddress((void**)&dinv, g_dinv);
    cudaGetSymbolAddress((void**)&T,    g_T);
    cudaGetSymbolAddress((void**)&h0,   g_h0);
    cudaGetSymbolAddress((void**)&h1,   g_h1);
    cudaGetSymbolAddress((void**)&xh,   g_xh);
    cudaGetSymbolAddress((void**)&bb1,  g_b1);
    cudaGetSymbolAddress((void**)&bb2,  g_b2);
    cudaGetSymbolAddress((void**)&bb3,  g_b3);
    cudaGetSymbolAddress((void**)&bb4,  g_b4);

    const int STAGE_BIG = 128 * 40 * 2 + 32 * 264 * 2;   // 27136
    const int SMEM_BIG  = 3 * STAGE_BIG;                 // 81408 (>= 64KB epi tile)
    const int STAGE64   = 128 * 40 * 2 + 32 * 72 * 2;    // 14848
    const int SMEM64    = (3 * STAGE64 > 128 * 64 * 4) ? 3 * STAGE64 : 128 * 64 * 4;  // 44544
    cudaFuncSetAttribute(gemm_big_kernel, cudaFuncAttributeMaxDynamicSharedMemorySize, SMEM_BIG);
    cudaFuncSetAttribute(gemm_n64_kernel, cudaFuncAttributeMaxDynamicSharedMemorySize, SMEM64);

    // ---- graph preprocessing + conversions ----
    detect_kernel<<<1, 32>>>(ei);
    zero_cnt_kernel<<<(N + 255) / 256, 256>>>(cnt, N);
    count_decomp_kernel<<<(CD_TOTAL + 255) / 256, 256>>>(
        ei, cnt, W1, W2, W3, W4, x, bb1, bb2, bb3, bb4, xh);
    scan1_kernel<<<SCAN_NB, SCAN_BLK>>>(cnt, off, bsum, N);
    scan2_kernel<<<1, SCAN_BLK>>>(bsum, off, SCAN_NB, N);
    scan3_kernel<<<(N + 255) / 256, 256>>>(cnt, off, cur, dinv, bsum, N);
    fill_kernel<<<(E + 255) / 256, 256>>>(ei, cur, srcs, E);
    sortseg_kernel<<<(N + 255) / 256, 256>>>(off, srcs, N);

    const int AGG_BLKS = (N_NODES + 7) / 8;  // 6250 (pad rows skipped)

    // L1: agg(xh, D=128) -> h0 ; gemm K=128 N=256 +b1+relu -> h1
    agg_h_kernel<128><<<AGG_BLKS, 256>>>(xh, off, srcs, dinv, nullptr, 0, h0);
    gemm_big_kernel<<<dim3(MT_COUNT, 1), 256, SMEM_BIG>>>(h0, bb1, b1, 1, h1, 128, 256);

    // L2: agg(h1, D=256) -> h0 ; gemm K=256 N=512 +b2+relu -> h1
    agg_h_kernel<256><<<AGG_BLKS, 256>>>(h1, off, srcs, dinv, nullptr, 0, h0);
    gemm_big_kernel<<<dim3(MT_COUNT, 2), 256, SMEM_BIG>>>(h0, bb2, b2, 1, h1, 256, 512);

    // L3: gemm K=512 N=256 -> h0 ; agg(+b3+relu) -> h1
    gemm_big_kernel<<<dim3(MT_COUNT, 1), 256, SMEM_BIG>>>(h1, bb3, nullptr, 0, h0, 512, 256);
    agg_h_kernel<256><<<AGG_BLKS, 256>>>(h0, off, srcs, dinv, b3, 1, h1);

    // L4: gemm K=256 N=64 -> h0 ; fused agg(+b4+relu) + [64,2] gemm -> T
    gemm_n64_kernel<<<MT_COUNT, 256, SMEM64>>>(h1, bb4, h0, 256, 64);
    agg64_gemm2_kernel<<<(N + 7) / 8, 256>>>(h0, off, srcs, dinv, b4, W5, T, N);

    // L5: agg(dim 2) + b5 + log_softmax -> out
    agg2_lsm_kernel<<<(N + 255) / 256, 256>>>(T, b5, out, off, srcs, dinv, N);
}

// round 17
// speedup vs baseline: 1.0599x; 1.0599x over previous
#include <cuda_runtime.h>
#include <cuda_fp16.h>
#include <mma.h>
#include <math.h>
#include <stdint.h>

using namespace nvcuda;

#define N_NODES 50000
#define N_EDGES 400000
#define MT_COUNT 392                 // padded row tiles: 392*128 = 50176
#define PAD_ROWS (MT_COUNT * 128)
#define SCAN_BLK 256
#define SCAN_NB ((N_NODES + SCAN_BLK - 1) / SCAN_BLK)

typedef unsigned int u32;
typedef unsigned long long u64;

// ---------------- scratch (static device globals; no allocs) ----------------
__device__ int   g_is64;
__device__ int   g_cnt[N_NODES];
__device__ int   g_off[N_NODES + 1];
__device__ int   g_cur[N_NODES];
__device__ int   g_srcs[N_EDGES];
__device__ int   g_bsum[SCAN_BLK];
__device__ float g_dinv[N_NODES];
__device__ float g_T[2 * N_NODES];
// fp16 activation ping-pong buffers, row-major [PAD_ROWS, <=512]
__device__ __half g_h0[(size_t)PAD_ROWS * 512];
__device__ __half g_h1[(size_t)PAD_ROWS * 512];
// x converted to fp16 [N_NODES,128]
__device__ __half g_xh[(size_t)N_NODES * 128];
// weights fp16
__device__ __half g_b1[128 * 256];
__device__ __half g_b2[256 * 512];
__device__ __half g_b3[512 * 256];
__device__ __half g_b4[256 * 64];

// ---------------- helpers ----------------
__device__ __forceinline__ u32 smem_u32(const void* p) {
    return (u32)__cvta_generic_to_shared(p);
}
__device__ __forceinline__ void cp_async16(u32 dst, const void* src) {
    asm volatile("cp.async.cg.shared.global [%0], [%1], 16;" :: "r"(dst), "l"(src));
}
__device__ __forceinline__ void cp_commit() {
    asm volatile("cp.async.commit_group;" ::: "memory");
}
__device__ __forceinline__ void cp_wait_dyn(int n) {
    if (n <= 0)      asm volatile("cp.async.wait_group 0;" ::: "memory");
    else if (n == 1) asm volatile("cp.async.wait_group 1;" ::: "memory");
    else             asm volatile("cp.async.wait_group 2;" ::: "memory");
}
template <int F2>
__device__ __forceinline__ void load_h2v(const __half2* p, __half2* v) {
    if (F2 == 1)      *(u32*)v  = *(const u32*)p;
    else if (F2 == 2) *(uint2*)v = *(const uint2*)p;
    else              *(uint4*)v = *(const uint4*)p;
}
template <int F2>
__device__ __forceinline__ void store_h2v(__half2* p, const __half2* v) {
    if (F2 == 1)      *(u32*)p  = *(const u32*)v;
    else if (F2 == 2) *(uint2*)p = *(const uint2*)v;
    else              *(uint4*)p = *(const uint4*)v;
}

// ---------------- edge dtype detection (warp-parallel) ----------------
__global__ void detect_kernel(const void* eiv) {
    const long long* p = (const long long*)eiv;
    int t = threadIdx.x;
    int bad = 0;
    #pragma unroll
    for (int e = t; e < 256; e += 32) {
        long long v = p[e];
        if (v < 0 || v >= N_NODES) bad = 1;
    }
    unsigned m = __ballot_sync(0xFFFFFFFFu, bad);
    if (t == 0) g_is64 = (m == 0u);
}
__device__ __forceinline__ int load_src(const void* eiv, int E, int e) {
    return g_is64 ? (int)((const long long*)eiv)[e] : ((const int*)eiv)[e];
}
__device__ __forceinline__ int load_dst(const void* eiv, int E, int e) {
    return g_is64 ? (int)((const long long*)eiv)[E + e] : ((const int*)eiv)[E + e];
}

// ---------------- preprocessing ----------------
__global__ void zero_cnt_kernel(int* cnt, int n) {
    int i = blockIdx.x * blockDim.x + threadIdx.x;
    if (i < n) cnt[i] = 0;
}
__global__ void count_kernel(const void* __restrict__ eiv, int* cnt, int E) {
    int e = blockIdx.x * blockDim.x + threadIdx.x;
    if (e < E) atomicAdd(&cnt[load_dst(eiv, E, e)], 1);
}
__global__ void scan1_kernel(const int* __restrict__ cnt, int* __restrict__ off,
                             int* __restrict__ bsum, int n) {
    __shared__ int sh[SCAN_BLK];
    int t = threadIdx.x;
    int i = blockIdx.x * SCAN_BLK + t;
    int v = (i < n) ? cnt[i] : 0;
    sh[t] = v;
    __syncthreads();
    for (int d = 1; d < SCAN_BLK; d <<= 1) {
        int x = 0;
        if (t >= d) x = sh[t - d];
        __syncthreads();
        if (t >= d) sh[t] += x;
        __syncthreads();
    }
    if (i < n) off[i] = sh[t] - v;
    if (t == SCAN_BLK - 1) bsum[blockIdx.x] = sh[t];
}
__global__ void scan2_kernel(int* __restrict__ bsum, int* __restrict__ off, int nb, int n) {
    __shared__ int sh[SCAN_BLK];
    int t = threadIdx.x;
    int v = (t < nb) ? bsum[t] : 0;
    sh[t] = v;
    __syncthreads();
    for (int d = 1; d < SCAN_BLK; d <<= 1) {
        int x = 0;
        if (t >= d) x = sh[t - d];
        __syncthreads();
        if (t >= d) sh[t] += x;
        __syncthreads();
    }
    if (t < nb) bsum[t] = sh[t] - v;
    if (t == nb - 1) off[n] = sh[t];
}
__global__ void scan3_kernel(const int* __restrict__ cnt, int* __restrict__ off,
                             int* __restrict__ cur, float* __restrict__ dinv,
                             const int* __restrict__ bsum, int n) {
    int i = blockIdx.x * blockDim.x + threadIdx.x;
    if (i < n) {
        int o = off[i] + bsum[i >> 8];
        off[i] = o;
        cur[i] = o;
        dinv[i] = rsqrtf((float)(cnt[i] + 1));
    }
}
__global__ void fill_kernel(const void* __restrict__ eiv, int* cur,
                            int* __restrict__ srcs, int E) {
    int e = blockIdx.x * blockDim.x + threadIdx.x;
    if (e < E) {
        int d = load_dst(eiv, E, e);
        int pos = atomicAdd(&cur[d], 1);
        srcs[pos] = load_src(eiv, E, e);
    }
}
__global__ void sortseg_kernel(const int* __restrict__ off, int* __restrict__ srcs, int n) {
    int i = blockIdx.x * blockDim.x + threadIdx.x;
    if (i >= n) return;
    int s0 = off[i], s1 = off[i + 1];
    for (int a = s0 + 1; a < s1; ++a) {
        int key = srcs[a];
        int b = a - 1;
        while (b >= s0 && srcs[b] > key) { srcs[b + 1] = srcs[b]; --b; }
        srcs[b + 1] = key;
    }
}

// ---------------- fused vectorized conversion: W1..W4 and x -> fp16 ----------------
#define W1_SZ (128 * 256)
#define W2_SZ (256 * 512)
#define W3_SZ (512 * 256)
#define W4_SZ (256 * 64)
#define X_SZ  (N_NODES * 128)
#define CONV_TOTAL4 ((W1_SZ + W2_SZ + W3_SZ + W4_SZ + X_SZ) / 4)
__device__ __forceinline__ void conv4(const float* __restrict__ S, __half* __restrict__ D, int e4) {
    float4 v = *(const float4*)(S + 4 * e4);
    __half2 p0; p0.x = __float2half(v.x); p0.y = __float2half(v.y);
    __half2 p1; p1.x = __float2half(v.z); p1.y = __float2half(v.w);
    *(__half2*)(D + 4 * e4) = p0;
    *(__half2*)(D + 4 * e4 + 2) = p1;
}
__global__ void decomp_all_kernel(const float* __restrict__ W1, const float* __restrict__ W2,
                                  const float* __restrict__ W3, const float* __restrict__ W4,
                                  const float* __restrict__ X,
                                  __half* __restrict__ B1, __half* __restrict__ B2,
                                  __half* __restrict__ B3, __half* __restrict__ B4,
                                  __half* __restrict__ XH) {
    int e = blockIdx.x * blockDim.x + threadIdx.x;
    if (e < W1_SZ / 4) { conv4(W1, B1, e); return; }
    e -= W1_SZ / 4;
    if (e < W2_SZ / 4) { conv4(W2, B2, e); return; }
    e -= W2_SZ / 4;
    if (e < W3_SZ / 4) { conv4(W3, B3, e); return; }
    e -= W3_SZ / 4;
    if (e < W4_SZ / 4) { conv4(W4, B4, e); return; }
    e -= W4_SZ / 4;
    if (e < X_SZ / 4) conv4(X, XH, e);
}

// ---------------- aggregation (fp16 in, fp16 out, fp32 accumulate) ----------------
// out[i] = dinv[i]*(dinv[i]*h[i] + sum dinv[s]*h[s]) (+bias, relu)
// Warp per node, 8 warps/block, no smem/barriers. Lane handles F2 half2's.
template <int D>
__global__ __launch_bounds__(256) void agg_h_kernel(
    const __half* __restrict__ H,
    const int* __restrict__ off, const int* __restrict__ srcs,
    const float* __restrict__ dinv,
    const float* __restrict__ bias, int doRelu, int nTotal,
    __half* __restrict__ Oh) {
    constexpr int F2 = D / 64;          // half2 per lane
    int lane = threadIdx.x & 31;
    int i = blockIdx.x * 8 + (threadIdx.x >> 5);
    if (i >= nTotal) return;

    float2 vo[F2];
    #pragma unroll
    for (int j = 0; j < F2; ++j) { vo[j].x = 0.0f; vo[j].y = 0.0f; }

    if (i < N_NODES) {
        float di = dinv[i];
        float2 acc[F2], acc2[F2];
        {
            __half2 h[F2];
            load_h2v<F2>((const __half2*)(H + (size_t)i * D) + lane * F2, h);
            #pragma unroll
            for (int j = 0; j < F2; ++j) {
                float2 f = __half22float2(h[j]);
                acc[j].x = di * f.x; acc[j].y = di * f.y;
                acc2[j].x = 0.0f; acc2[j].y = 0.0f;
            }
        }
        int s0 = off[i], s1 = off[i + 1];
        for (int base = s0; base < s1; base += 32) {
            int nb = s1 - base; if (nb > 32) nb = 32;
            int sid = 0; float wv = 0.0f;
            if (lane < nb) { sid = srcs[base + lane]; wv = dinv[sid]; }
            int e = 0;
            for (; e + 1 < nb; e += 2) {
                int sa = __shfl_sync(0xFFFFFFFFu, sid, e);
                float wa = __shfl_sync(0xFFFFFFFFu, wv, e);
                int sb = __shfl_sync(0xFFFFFFFFu, sid, e + 1);
                float wb = __shfl_sync(0xFFFFFFFFu, wv, e + 1);
                __half2 ha[F2], hb[F2];
                load_h2v<F2>((const __half2*)(H + (size_t)sa * D) + lane * F2, ha);
                load_h2v<F2>((const __half2*)(H + (size_t)sb * D) + lane * F2, hb);
                #pragma unroll
                for (int j = 0; j < F2; ++j) {
                    float2 fa = __half22float2(ha[j]);
                    float2 fb = __half22float2(hb[j]);
                    acc[j].x  = fmaf(wa, fa.x, acc[j].x);
                    acc[j].y  = fmaf(wa, fa.y, acc[j].y);
                    acc2[j].x = fmaf(wb, fb.x, acc2[j].x);
                    acc2[j].y = fmaf(wb, fb.y, acc2[j].y);
                }
            }
            if (e < nb) {
                int sa = __shfl_sync(0xFFFFFFFFu, sid, e);
                float wa = __shfl_sync(0xFFFFFFFFu, wv, e);
                __half2 ha[F2];
                load_h2v<F2>((const __half2*)(H + (size_t)sa * D) + lane * F2, ha);
                #pragma unroll
                for (int j = 0; j < F2; ++j) {
                    float2 fa = __half22float2(ha[j]);
                    acc[j].x = fmaf(wa, fa.x, acc[j].x);
                    acc[j].y = fmaf(wa, fa.y, acc[j].y);
                }
            }
        }
        #pragma unroll
        for (int j = 0; j < F2; ++j) {
            float v0 = di * (acc[j].x + acc2[j].x);
            float v1 = di * (acc[j].y + acc2[j].y);
            if (bias) {
                v0 += bias[(lane * F2 + j) * 2];
                v1 += bias[(lane * F2 + j) * 2 + 1];
            }
            if (doRelu) { v0 = fmaxf(v0, 0.0f); v1 = fmaxf(v1, 0.0f); }
            vo[j].x = v0; vo[j].y = v1;
        }
    }
    __half2 oh[F2];
    #pragma unroll
    for (int j = 0; j < F2; ++j) oh[j] = __float22half2_rn(vo[j]);
    store_h2v<F2>((__half2*)(Oh + (size_t)i * D) + lane * F2, oh);
}

// ---------------- fused L4 agg + [64,2] GEMM ----------------
__global__ __launch_bounds__(256) void agg64_gemm2_kernel(
    const __half* __restrict__ H,
    const int* __restrict__ off, const int* __restrict__ srcs,
    const float* __restrict__ dinv,
    const float* __restrict__ b4, const float* __restrict__ W5,
    float* __restrict__ T, int nTotal) {
    int lane = threadIdx.x & 31;
    int i = blockIdx.x * 8 + (threadIdx.x >> 5);
    if (i >= nTotal) return;
    float di = dinv[i];
    float2 f = __half22float2(*((const __half2*)(H + (size_t)i * 64) + lane));
    float a0 = di * f.x, a1 = di * f.y, c0 = 0.f, c1 = 0.f;
    int s0 = off[i], s1 = off[i + 1];
    for (int base = s0; base < s1; base += 32) {
        int nb = s1 - base; if (nb > 32) nb = 32;
        int sid = 0; float wv = 0.0f;
        if (lane < nb) { sid = srcs[base + lane]; wv = dinv[sid]; }
        int e = 0;
        for (; e + 1 < nb; e += 2) {
            int sa = __shfl_sync(0xFFFFFFFFu, sid, e);
            float wa = __shfl_sync(0xFFFFFFFFu, wv, e);
            int sb = __shfl_sync(0xFFFFFFFFu, sid, e + 1);
            float wb = __shfl_sync(0xFFFFFFFFu, wv, e + 1);
            float2 fa = __half22float2(*((const __half2*)(H + (size_t)sa * 64) + lane));
            float2 fb = __half22float2(*((const __half2*)(H + (size_t)sb * 64) + lane));
            a0 = fmaf(wa, fa.x, a0); a1 = fmaf(wa, fa.y, a1);
            c0 = fmaf(wb, fb.x, c0); c1 = fmaf(wb, fb.y, c1);
        }
        if (e < nb) {
            int sa = __shfl_sync(0xFFFFFFFFu, sid, e);
            float wa = __shfl_sync(0xFFFFFFFFu, wv, e);
            float2 fa = __half22float2(*((const __half2*)(H + (size_t)sa * 64) + lane));
            a0 = fmaf(wa, fa.x, a0); a1 = fmaf(wa, fa.y, a1);
        }
    }
    float v0 = di * (a0 + c0) + b4[lane * 2];
    float v1 = di * (a1 + c1) + b4[lane * 2 + 1];
    v0 = fmaxf(v0, 0.0f); v1 = fmaxf(v1, 0.0f);
    float4 w = *(const float4*)(W5 + 4 * lane);
    float p0 = v0 * w.x + v1 * w.z;
    float p1 = v0 * w.y + v1 * w.w;
    #pragma unroll
    for (int o = 16; o > 0; o >>= 1) {
        p0 += __shfl_down_sync(0xFFFFFFFFu, p0, o);
        p1 += __shfl_down_sync(0xFFFFFFFFu, p1, o);
    }
    if (lane == 0) { T[2 * i] = p0; T[2 * i + 1] = p1; }
}

// ---------------- WMMA fp16 GEMM, BK=32, 3-stage pipeline, single sync per k-step ----------------
template <int BN>
__global__ __launch_bounds__(256) void gemm_wmma_kernel(
    const __half* __restrict__ Ah, const __half* __restrict__ Bh,
    const float* __restrict__ bias, int doRelu,
    __half* __restrict__ Oh, int K, int N) {
    constexpr int A_LD = 40;            // 32 + 8 pad (halves)
    constexpr int B_LD = BN + 8;
    constexpr int A_BYTES = 128 * A_LD * 2;
    constexpr int STAGE = A_BYTES + 32 * B_LD * 2;
    constexpr int WN = BN / 2;
    constexpr int NF = WN / 16;

    extern __shared__ char sm[];
    int tid = threadIdx.x;
    int wid = tid >> 5;
    int mt = blockIdx.x, nt = blockIdx.y;
    int row0 = mt * 128, bn0 = nt * BN;
    int total = K >> 5;

    auto As = [&](int s) { return (__half*)(sm + s * STAGE); };
    auto Bs = [&](int s) { return (__half*)(sm + s * STAGE + A_BYTES); };

    auto issue = [&](int u) {
        int s = u % 3;
        int k0 = u << 5;
        #pragma unroll
        for (int c = 0; c < 2; ++c) {
            int chunk = tid + c * 256;
            int row = chunk >> 2, col8 = (chunk & 3) * 8;
            u32 dst = smem_u32(As(s) + row * A_LD + col8);
            cp_async16(dst, Ah + (size_t)(row0 + row) * K + k0 + col8);
        }
        constexpr int NCB = 32 * BN / 8 / 256;
        #pragma unroll
        for (int c = 0; c < NCB; ++c) {
            int chunk = tid + c * 256;
            int r = chunk / (BN / 8), c8 = (chunk % (BN / 8)) * 8;
            u32 dst = smem_u32(Bs(s) + r * B_LD + c8);
            cp_async16(dst, Bh + (size_t)(k0 + r) * N + bn0 + c8);
        }
        cp_commit();
    };

    int wm = (wid & 3) * 32;
    int wn = (wid >> 2) * WN;

    wmma::fragment<wmma::accumulator, 16, 16, 16, float> acc[2][NF];
    #pragma unroll
    for (int mi = 0; mi < 2; ++mi)
        #pragma unroll
        for (int ni = 0; ni < NF; ++ni) wmma::fill_fragment(acc[mi][ni], 0.0f);

    int issued = 0;
    for (int p = 0; p < 2 && issued < total; ++p) issue(issued++);
    for (int u = 0; u < total; ++u) {
        cp_wait_dyn(issued - u - 1);
        // Single barrier: stage u's data is visible AND every thread finished
        // computing stage u-1 == ring slot (u+2)%3, so refilling it is race-free.
        __syncthreads();
        if (issued < total) issue(issued++);
        int s = u % 3;
        const __half* a = As(s);
        const __half* b = Bs(s);
        #pragma unroll
        for (int kf = 0; kf < 2; ++kf) {
            wmma::fragment<wmma::matrix_a, 16, 16, 16, __half, wmma::row_major> af[2];
            wmma::fragment<wmma::matrix_b, 16, 16, 16, __half, wmma::row_major> bf[NF];
            #pragma unroll
            for (int mi = 0; mi < 2; ++mi)
                wmma::load_matrix_sync(af[mi], a + (wm + mi * 16) * A_LD + kf * 16, A_LD);
            #pragma unroll
            for (int ni = 0; ni < NF; ++ni)
                wmma::load_matrix_sync(bf[ni], b + (kf * 16) * B_LD + wn + ni * 16, B_LD);
            #pragma unroll
            for (int mi = 0; mi < 2; ++mi)
                #pragma unroll
                for (int ni = 0; ni < NF; ++ni)
                    wmma::mma_sync(acc[mi][ni], af[mi], bf[ni], acc[mi][ni]);
        }
    }
    __syncthreads();  // protect epilogue smem reuse

    // epilogue via smem (fp32 tile), write fp16 vectorized
    float* Cs = (float*)sm;
    #pragma unroll
    for (int mi = 0; mi < 2; ++mi)
        #pragma unroll
        for (int ni = 0; ni < NF; ++ni)
            wmma::store_matrix_sync(Cs + (wm + mi * 16) * BN + wn + ni * 16,
                                    acc[mi][ni], BN, wmma::mem_row_major);
    __syncthreads();

    for (int idx2 = tid; idx2 < 128 * BN / 2; idx2 += 256) {
        int r = idx2 / (BN / 2), c2 = idx2 % (BN / 2);
        float v0 = Cs[r * BN + 2 * c2];
        float v1 = Cs[r * BN + 2 * c2 + 1];
        if (bias) { v0 += bias[bn0 + 2 * c2]; v1 += bias[bn0 + 2 * c2 + 1]; }
        if (doRelu) { v0 = fmaxf(v0, 0.0f); v1 = fmaxf(v1, 0.0f); }
        __half2 p; p.x = __float2half(v0); p.y = __float2half(v1);
        *(__half2*)(Oh + (size_t)(row0 + r) * N + bn0 + 2 * c2) = p;
    }
}

// ---------------- final aggregation (dim 2) + bias + log_softmax ----------------
__global__ void agg2_lsm_kernel(const float* __restrict__ T, const float* __restrict__ b,
                                float* __restrict__ out,
                                const int* __restrict__ off, const int* __restrict__ srcs,
                                const float* __restrict__ dinv, int n) {
    int i = blockIdx.x * blockDim.x + threadIdx.x;
    if (i >= n) return;
    float di = dinv[i];
    float a0 = di * T[2 * i];
    float a1 = di * T[2 * i + 1];
    int s0 = off[i], s1 = off[i + 1];
    for (int e = s0; e < s1; ++e) {
        int s = srcs[e];
        float w = dinv[s];
        a0 = fmaf(w, T[2 * s], a0);
        a1 = fmaf(w, T[2 * s + 1], a1);
    }
    float z0 = fmaf(di, a0, b[0]);
    float z1 = fmaf(di, a1, b[1]);
    float m = fmaxf(z0, z1);
    float lse = m + logf(expf(z0 - m) + expf(z1 - m));
    out[2 * i] = z0 - lse;
    out[2 * i + 1] = z1 - lse;
}

// ---------------- host launch ----------------
extern "C" void kernel_launch(void* const* d_in, const int* in_sizes, int n_in,
                              void* d_out, int out_size) {
    const float* x  = (const float*)d_in[0];
    const void*  ei = d_in[1];
    const float* W1 = (const float*)d_in[2];  const float* b1 = (const float*)d_in[3];
    const float* W2 = (const float*)d_in[4];  const float* b2 = (const float*)d_in[5];
    const float* W3 = (const float*)d_in[6];  const float* b3 = (const float*)d_in[7];
    const float* W4 = (const float*)d_in[8];  const float* b4 = (const float*)d_in[9];
    const float* W5 = (const float*)d_in[10]; const float* b5 = (const float*)d_in[11];
    float* out = (float*)d_out;

    const int N = N_NODES;
    const int E = N_EDGES;

    int *cnt, *off, *cur, *srcs, *bsum;
    float *dinv, *T;
    __half *h0, *h1, *xh, *bb1, *bb2, *bb3, *bb4;
    cudaGetSymbolAddress((void**)&cnt,  g_cnt);
    cudaGetSymbolAddress((void**)&off,  g_off);
    cudaGetSymbolAddress((void**)&cur,  g_cur);
    cudaGetSymbolAddress((void**)&srcs, g_srcs);
    cudaGetSymbolAddress((void**)&bsum, g_bsum);
    cudaGetSymbolAddress((void**)&dinv, g_dinv);
    cudaGetSymbolAddress((void**)&T,    g_T);
    cudaGetSymbolAddress((void**)&h0,   g_h0);
    cudaGetSymbolAddress((void**)&h1,   g_h1);
    cudaGetSymbolAddress((void**)&xh,   g_xh);
    cudaGetSymbolAddress((void**)&bb1,  g_b1);
    cudaGetSymbolAddress((void**)&bb2,  g_b2);
    cudaGetSymbolAddress((void**)&bb3,  g_b3);
    cudaGetSymbolAddress((void**)&bb4,  g_b4);

    const int STAGE128 = 128 * 40 * 2 + 32 * 136 * 2;  // 18944
    const int STAGE64  = 128 * 40 * 2 + 32 * 72 * 2;   // 14848
    const int SMEM128 = (3 * STAGE128 > 128 * 128 * 4) ? 3 * STAGE128 : 128 * 128 * 4;  // 65536
    const int SMEM64  = (3 * STAGE64 > 128 * 64 * 4) ? 3 * STAGE64 : 128 * 64 * 4;      // 44544
    cudaFuncSetAttribute(gemm_wmma_kernel<128>, cudaFuncAttributeMaxDynamicSharedMemorySize, SMEM128);
    cudaFuncSetAttribute(gemm_wmma_kernel<64>,  cudaFuncAttributeMaxDynamicSharedMemorySize, SMEM64);

    // ---- graph preprocessing + conversions (measured-best R10 ordering) ----
    detect_kernel<<<1, 32>>>(ei);
    zero_cnt_kernel<<<(N + 255) / 256, 256>>>(cnt, N);
    count_kernel<<<(E + 255) / 256, 256>>>(ei, cnt, E);
    decomp_all_kernel<<<(CONV_TOTAL4 + 255) / 256, 256>>>(
        W1, W2, W3, W4, x, bb1, bb2, bb3, bb4, xh);
    scan1_kernel<<<SCAN_NB, SCAN_BLK>>>(cnt, off, bsum, N);
    scan2_kernel<<<1, SCAN_BLK>>>(bsum, off, SCAN_NB, N);
    scan3_kernel<<<(N + 255) / 256, 256>>>(cnt, off, cur, dinv, bsum, N);
    fill_kernel<<<(E + 255) / 256, 256>>>(ei, cur, srcs, E);
    sortseg_kernel<<<(N + 255) / 256, 256>>>(off, srcs, N);

    const int AGG_BLKS = (PAD_ROWS + 7) / 8;  // 6272

    // L1: agg(xh, D=128) -> h0 ; gemm K=128 N=256 +b1+relu -> h1
    agg_h_kernel<128><<<AGG_BLKS, 256>>>(xh, off, srcs, dinv, nullptr, 0, PAD_ROWS, h0);
    gemm_wmma_kernel<128><<<dim3(MT_COUNT, 2), 256, SMEM128>>>(h0, bb1, b1, 1, h1, 128, 256);

    // L2: agg(h1, D=256) -> h0 ; gemm K=256 N=512 +b2+relu -> h1
    agg_h_kernel<256><<<AGG_BLKS, 256>>>(h1, off, srcs, dinv, nullptr, 0, PAD_ROWS, h0);
    gemm_wmma_kernel<128><<<dim3(MT_COUNT, 4), 256, SMEM128>>>(h0, bb2, b2, 1, h1, 256, 512);

    // L3: gemm K=512 N=256 -> h0 ; agg(+b3+relu) -> h1
    gemm_wmma_kernel<128><<<dim3(MT_COUNT, 2), 256, SMEM128>>>(h1, bb3, nullptr, 0, h0, 512, 256);
    agg_h_kernel<256><<<AGG_BLKS, 256>>>(h0, off, srcs, dinv, b3, 1, PAD_ROWS, h1);

    // L4: gemm K=256 N=64 -> h0 ; fused agg(+b4+relu) + [64,2] gemm -> T
    gemm_wmma_kernel<64><<<dim3(MT_COUNT, 1), 256, SMEM64>>>(h1, bb4, nullptr, 0, h0, 256, 64);
    agg64_gemm2_kernel<<<(N + 7) / 8, 256>>>(h0, off, srcs, dinv, b4, W5, T, N);

    // L5: agg(dim 2) + b5 + log_softmax -> out
    agg2_lsm_kernel<<<(N + 255) / 256, 256>>>(T, b5, out, off, srcs, dinv, N);
}